// round 8
// baseline (speedup 1.0000x reference)
#include <cuda_runtime.h>
#include <cuda_fp16.h>
#include <cstdint>

// Problem constants
#define N_TOK   4096
#define C_BOOKS 128
#define K_CENT  16
#define V_LEN   16
#define IN_DIM  2048
#define OUT_DIM 4096
#define KTOT    2048                   // 128 books * 16 centroids (one-hot K)

// Scratch (allocation-free rule: device globals)
__device__ unsigned char g_idxT[(size_t)C_BOOKS * N_TOK];   // [c][token]
__device__ __half g_Bt[(size_t)OUT_DIM * KTOT];             // [o][k] k-contiguous, 16 MB
__device__ int g_mode;                                      // sparse metadata mode (255 = none)

// ---------------------------------------------------------------------------
__device__ __forceinline__ uint32_t smem_u32(const void* p) {
    uint32_t a;
    asm("{ .reg .u64 t; cvta.to.shared.u64 t, %1; cvt.u32.u64 %0, t; }" : "=r"(a) : "l"(p));
    return a;
}
// dense one-hot half2: t==0 -> (1,0), t==1 -> (0,1), else (0,0)
__device__ __forceinline__ uint32_t oh(uint32_t t) {
    return t == 0u ? 0x3C00u : (t == 1u ? 0x3C000000u : 0u);
}
// sparse A value half2 for compressed col pair of group t: u = idx ^ (4t)
__device__ __forceinline__ uint32_t ohs(uint32_t u) {
    return u > 3u ? 0u : (u == 3u ? 0x3C000000u : 0x3C00u);
}
// 16-bit metadata halfword: 4 groups, default indices {0,1}; nonzero group
// q=p>>2 gets indices {off,3} (off<3) or {0,3} (off==3), ascending order.
__device__ __forceinline__ uint32_t h16m(uint32_t p) {
    uint32_t q = p >> 2, o = p & 3;
    uint32_t nz = 12u + (o == 3u ? 0u : o);
    return (0x4444u & ~(0xFu << (q * 4))) | (nz << (q * 4));
}
// Candidate metadata word for one k32 tile (rows a=low, b=high of the m16).
// p0* = cb0 idx bytes, p1* = cb1 idx bytes.
__device__ __forceinline__ uint32_t build_e(int mode, int lane,
    uint32_t p0a, uint32_t p0b, uint32_t p1a, uint32_t p1b)
{
    int sel = (mode >= 4) ? ((lane >> 1) & 1) : (lane & 1);
    if (mode == 0 || mode == 2 || mode == 4) {          // row-split: full row per word
        int r = sel ^ (mode == 2 ? 1 : 0);
        uint32_t x0 = r ? p0b : p0a, x1 = r ? p1b : p1a;
        return h16m(x0) | (h16m(x1) << 16);
    } else {                                            // cb-split: one cb, both rows
        uint32_t c0 = sel ? p1a : p0a, c1 = sel ? p1b : p0b;
        if (mode == 3) { uint32_t t = c0; c0 = c1; c1 = t; }
        return h16m(c0) | (h16m(c1) << 16);
    }
}

#define MMA_SP(d, a0, a1, a2, a3, b0, b1, b2, b3, e) \
    asm volatile("mma.sp.sync.aligned.m16n8k32.row.col.f32.f16.f16.f32 " \
        "{%0,%1,%2,%3}, {%4,%5,%6,%7}, {%8,%9,%10,%11}, {%0,%1,%2,%3}, %12, 0x0;" \
        : "+f"((d)[0]), "+f"((d)[1]), "+f"((d)[2]), "+f"((d)[3]) \
        : "r"(a0), "r"(a1), "r"(a2), "r"(a3), \
          "r"(b0), "r"(b1), "r"(b2), "r"(b3), "r"(e))

#define MMA(d, a0, a1, a2, a3, b0, b1) \
    asm volatile("mma.sync.aligned.m16n8k16.row.col.f32.f16.f16.f32 " \
        "{%0,%1,%2,%3}, {%4,%5,%6,%7}, {%8,%9}, {%0,%1,%2,%3};" \
        : "+f"((d)[0]), "+f"((d)[1]), "+f"((d)[2]), "+f"((d)[3]) \
        : "r"(a0), "r"(a1), "r"(a2), "r"(a3), "r"(b0), "r"(b1))

// ---------------------------------------------------------------------------
// Probe: discover the mma.sp metadata layout empirically. 1 warp.
// A: one-hot rows with idx0[r]=(3r+1)&15 (cb0), idx1[r]=(5r+2)&15 (cb1).
// B[k][n] = k+1 (n-independent). D[r][n] must equal (idx0[r]+1)+(idx1[r]+17).
// ---------------------------------------------------------------------------
__global__ void probe_sp_kernel()
{
    int lane = threadIdx.x & 31;
    int g = lane >> 2, t = lane & 3;
    uint32_t p0a = (uint32_t)((3 * g + 1) & 15);
    uint32_t p0b = (uint32_t)((3 * (g + 8) + 1) & 15);
    uint32_t p1a = (uint32_t)((5 * g + 2) & 15);
    uint32_t p1b = (uint32_t)((5 * (g + 8) + 2) & 15);
    uint32_t tx = (uint32_t)(t << 2);
    uint32_t a0 = ohs(p0a ^ tx), a1 = ohs(p0b ^ tx);
    uint32_t a2 = ohs(p1a ^ tx), a3 = ohs(p1b ^ tx);

    __half2 hb0 = __floats2half2_rn((float)(2*t+1),  (float)(2*t+2));
    __half2 hb1 = __floats2half2_rn((float)(2*t+9),  (float)(2*t+10));
    __half2 hb2 = __floats2half2_rn((float)(2*t+17), (float)(2*t+18));
    __half2 hb3 = __floats2half2_rn((float)(2*t+25), (float)(2*t+26));
    uint32_t b0 = *(uint32_t*)&hb0, b1 = *(uint32_t*)&hb1;
    uint32_t b2 = *(uint32_t*)&hb2, b3 = *(uint32_t*)&hb3;

    float eg = (float)(p0a + 1u) + (float)(p1a + 17u);
    float eh = (float)(p0b + 1u) + (float)(p1b + 17u);

    int found = 255;
    for (int m = 0; m < 6; ++m) {
        uint32_t e = build_e(m, lane, p0a, p0b, p1a, p1b);
        float d[4] = {0.f, 0.f, 0.f, 0.f};
        MMA_SP(d, a0, a1, a2, a3, b0, b1, b2, b3, e);
        bool ok = (d[0] == eg) && (d[1] == eg) && (d[2] == eh) && (d[3] == eh);
        if (__all_sync(0xffffffffu, ok) && found == 255) found = m;
    }
    if (lane == 0) g_mode = found;
}

// ---------------------------------------------------------------------------
// Kernel A: nearest-centroid indices (Chebyshev), exact vs reference argmin.
// ---------------------------------------------------------------------------
__global__ void __launch_bounds__(256) quant_idx_kernel(
    const float* __restrict__ x, const float* __restrict__ cents)
{
    __shared__ float sc[32 * 256];
    int tid = threadIdx.x, lane = tid & 31, w = tid >> 5;
    int token = blockIdx.x * 32 + lane;
    int cbase = blockIdx.y * 32;

    for (int i = tid; i < 32 * 256; i += 256)
        sc[i] = cents[(size_t)cbase * 256 + i];
    __syncthreads();

    const float* xrow = x + (size_t)token * IN_DIM;
    for (int cl = w * 4; cl < w * 4 + 4; ++cl) {
        int c = cbase + cl;
        float xv[16];
        const float4* xp = (const float4*)(xrow + c * V_LEN);
#pragma unroll
        for (int q = 0; q < 4; ++q) {
            float4 t = xp[q];
            xv[q*4+0] = t.x; xv[q*4+1] = t.y; xv[q*4+2] = t.z; xv[q*4+3] = t.w;
        }
        const float4* cb = (const float4*)(sc + cl * 256);
        float best = 3.4028235e38f; int bi = 0;
#pragma unroll
        for (int k = 0; k < K_CENT; ++k) {
            float d = 0.0f;
#pragma unroll
            for (int q = 0; q < 4; ++q) {
                float4 t = cb[k * 4 + q];
                d = fmaxf(d, fabsf(xv[q*4+0] - t.x));
                d = fmaxf(d, fabsf(xv[q*4+1] - t.y));
                d = fmaxf(d, fabsf(xv[q*4+2] - t.z));
                d = fmaxf(d, fabsf(xv[q*4+3] - t.w));
            }
            if (d < best) { best = d; bi = k; }   // strict < == first min (argmin)
        }
        g_idxT[(size_t)c * N_TOK + token] = (unsigned char)bi;
    }
}

// ---------------------------------------------------------------------------
// Kernel B: LUT -> fp16 B^T.
// ---------------------------------------------------------------------------
__global__ void __launch_bounds__(256) build_B_kernel(
    const float* __restrict__ wgt, const float* __restrict__ cents)
{
    __shared__ float sc[K_CENT * V_LEN];
    int c = blockIdx.x;
    int o = blockIdx.y * 256 + threadIdx.x;
    sc[threadIdx.x] = cents[(size_t)c * 256 + threadIdx.x];
    __syncthreads();

    float acc[K_CENT];
#pragma unroll
    for (int k = 0; k < K_CENT; ++k) acc[k] = 0.0f;
#pragma unroll
    for (int v = 0; v < V_LEN; ++v) {
        float wv = wgt[(size_t)(c * V_LEN + v) * OUT_DIM + o];
#pragma unroll
        for (int k = 0; k < K_CENT; ++k)
            acc[k] = fmaf(sc[k * V_LEN + v], wv, acc[k]);
    }
    __half2 h[8];
#pragma unroll
    for (int j = 0; j < 8; ++j)
        h[j] = __floats2half2_rn(acc[2 * j], acc[2 * j + 1]);
    uint4* dst = (uint4*)(g_Bt + (size_t)o * KTOT + c * 16);
    dst[0] = *(uint4*)&h[0];
    dst[1] = *(uint4*)&h[4];
}

// ---------------------------------------------------------------------------
// Shared GEMM layout constants (R4 skeleton)
// ---------------------------------------------------------------------------
#define SM_IDX  0
#define BSTG    (128 * 144)
#define SM_B    16384
#define SM_BIAS (SM_B + 2 * BSTG)       // 53248
#define SM_TOT  (SM_BIAS + 512)         // 53760

// ---------------------------------------------------------------------------
// Sparse GEMM (runs iff probe found a mode)
// ---------------------------------------------------------------------------
__global__ void __launch_bounds__(256, 1) onehot_sp_kernel(
    const float* __restrict__ bias, float* __restrict__ out)
{
    const int mode = *(volatile int*)&g_mode;
    if (mode == 255) return;

    extern __shared__ __align__(128) unsigned char smem[];
    const uint32_t sb = smem_u32(smem);
    const int tid = threadIdx.x, lane = tid & 31, w = tid >> 5;
    const int ms = w & 3, ns = w >> 2;
    const int m0 = blockIdx.y * 128, o0 = blockIdx.x * 128;

    {
        uint4* si = (uint4*)(smem + SM_IDX);
        for (int i = tid; i < 1024; i += 256)
            si[i] = *(const uint4*)(g_idxT + ((size_t)(i >> 3) << 12) + m0 + (i & 7) * 16);
        float* sbias = (float*)(smem + SM_BIAS);
        if (tid < 128) sbias[tid] = bias[o0 + tid];
    }

    const __half* gB = g_Bt + (size_t)o0 * KTOT;
#pragma unroll
    for (int s = 0; s < 2; ++s) {
        uint32_t dst = sb + SM_B + s * BSTG;
        const __half* src = gB + s * 64;
#pragma unroll
        for (int r = 0; r < 4; ++r) {
            int i = tid + r * 256, n = i >> 3, ch = i & 7;
            asm volatile("cp.async.cg.shared.global [%0], [%1], 16;"
                :: "r"(dst + n * 144 + ch * 16), "l"(src + (size_t)n * KTOT + ch * 8));
        }
        asm volatile("cp.async.commit_group;" ::: "memory");
    }

    float acc[2][8][4];
#pragma unroll
    for (int mf = 0; mf < 2; ++mf)
#pragma unroll
        for (int nf = 0; nf < 8; ++nf)
#pragma unroll
            for (int q = 0; q < 4; ++q) acc[mf][nf][q] = 0.0f;

    const uint32_t tx  = (uint32_t)((lane & 3) << 2);
    const uint32_t lmb = (uint32_t)((lane & 7) * 144 + (lane >> 3) * 16);
    const unsigned char* s_idx = smem + SM_IDX;
    const int rbase = ms * 32 + (lane >> 2);

    // Precompute mode selectors (uniform branches in loop)
    const int  sel   = (mode >= 4) ? ((lane >> 1) & 1) : (lane & 1);
    const bool rowsp = (mode == 0 || mode == 2 || mode == 4);
    const int  rinv  = sel ^ (mode == 2 ? 1 : 0);
    const bool swHL  = (mode == 3);

    for (int s = 0; s < 32; ++s) {
        asm volatile("cp.async.wait_group 1;" ::: "memory");
        __syncthreads();
        uint32_t bufB = sb + SM_B + (s & 1) * BSTG;
#pragma unroll
        for (int cbp = 0; cbp < 2; ++cbp) {
            int c = s * 4 + cbp * 2;
            const unsigned char* ip0 = s_idx + (c << 7) + rbase;
            const unsigned char* ip1 = ip0 + 128;
            uint32_t p0g = ip0[0], p0h = ip0[8], p0i = ip0[16], p0j = ip0[24];
            uint32_t p1g = ip1[0], p1h = ip1[8], p1i = ip1[16], p1j = ip1[24];
            uint32_t a00 = ohs(p0g ^ tx), a01 = ohs(p0h ^ tx);
            uint32_t a02 = ohs(p1g ^ tx), a03 = ohs(p1h ^ tx);
            uint32_t a10 = ohs(p0i ^ tx), a11 = ohs(p0j ^ tx);
            uint32_t a12 = ohs(p1i ^ tx), a13 = ohs(p1j ^ tx);
            uint32_t e0, e1;
            if (rowsp) {
                uint32_t x0 = rinv ? p0h : p0g, x1 = rinv ? p1h : p1g;
                uint32_t y0 = rinv ? p0j : p0i, y1 = rinv ? p1j : p1i;
                e0 = h16m(x0) | (h16m(x1) << 16);
                e1 = h16m(y0) | (h16m(y1) << 16);
            } else {
                uint32_t c0 = sel ? p1g : p0g, c1 = sel ? p1h : p0h;
                uint32_t d0 = sel ? p1i : p0i, d1 = sel ? p1j : p0j;
                if (swHL) { uint32_t t0 = c0; c0 = c1; c1 = t0; t0 = d0; d0 = d1; d1 = t0; }
                e0 = h16m(c0) | (h16m(c1) << 16);
                e1 = h16m(d0) | (h16m(d1) << 16);
            }
            uint32_t kb = bufB + (uint32_t)(cbp * 64) + (uint32_t)(ns * 64 * 144) + lmb;
#pragma unroll
            for (int nf = 0; nf < 8; ++nf) {
                uint32_t b0, b1, b2, b3;
                asm volatile("ldmatrix.sync.aligned.m8n8.x4.shared.b16 {%0,%1,%2,%3}, [%4];"
                             : "=r"(b0), "=r"(b1), "=r"(b2), "=r"(b3)
                             : "r"(kb + (uint32_t)(nf * 8 * 144)));
                MMA_SP(acc[0][nf], a00, a01, a02, a03, b0, b1, b2, b3, e0);
                MMA_SP(acc[1][nf], a10, a11, a12, a13, b0, b1, b2, b3, e1);
            }
        }
        __syncthreads();
        if (s + 2 < 32) {
            uint32_t dst = sb + SM_B + (s & 1) * BSTG;
            const __half* src = gB + (s + 2) * 64;
#pragma unroll
            for (int r = 0; r < 4; ++r) {
                int i = tid + r * 256, n = i >> 3, ch = i & 7;
                asm volatile("cp.async.cg.shared.global [%0], [%1], 16;"
                    :: "r"(dst + n * 144 + ch * 16), "l"(src + (size_t)n * KTOT + ch * 8));
            }
        }
        asm volatile("cp.async.commit_group;" ::: "memory");
    }

    const float* sbias = (const float*)(smem + SM_BIAS);
    const uint32_t c0 = (uint32_t)((lane & 3) * 2);
#pragma unroll
    for (int mf = 0; mf < 2; ++mf) {
        int row = m0 + ms * 32 + mf * 16 + (lane >> 2);
#pragma unroll
        for (int nf = 0; nf < 8; ++nf) {
            int colL = ns * 64 + nf * 8 + (int)c0;
            float2 bv = *(const float2*)(sbias + colL);
            float2 v0 = make_float2(acc[mf][nf][0] + bv.x, acc[mf][nf][1] + bv.y);
            float2 v1 = make_float2(acc[mf][nf][2] + bv.x, acc[mf][nf][3] + bv.y);
            *(float2*)(out + (size_t)row * OUT_DIM + o0 + colL) = v0;
            *(float2*)(out + (size_t)(row + 8) * OUT_DIM + o0 + colL) = v1;
        }
    }
}

// ---------------------------------------------------------------------------
// Dense GEMM fallback (verbatim R4; runs iff no sparse mode matched)
// ---------------------------------------------------------------------------
__global__ void __launch_bounds__(256, 1) onehot_dense_kernel(
    const float* __restrict__ bias, float* __restrict__ out)
{
    if (*(volatile int*)&g_mode != 255) return;

    extern __shared__ __align__(128) unsigned char smem[];
    const uint32_t sb = smem_u32(smem);
    const int tid = threadIdx.x, lane = tid & 31, w = tid >> 5;
    const int ms = w & 3, ns = w >> 2;
    const int m0 = blockIdx.y * 128, o0 = blockIdx.x * 128;

    {
        uint4* si = (uint4*)(smem + SM_IDX);
        for (int i = tid; i < 1024; i += 256)
            si[i] = *(const uint4*)(g_idxT + ((size_t)(i >> 3) << 12) + m0 + (i & 7) * 16);
        float* sbias = (float*)(smem + SM_BIAS);
        if (tid < 128) sbias[tid] = bias[o0 + tid];
    }

    const __half* gB = g_Bt + (size_t)o0 * KTOT;
#pragma unroll
    for (int s = 0; s < 2; ++s) {
        uint32_t dst = sb + SM_B + s * BSTG;
        const __half* src = gB + s * 64;
#pragma unroll
        for (int r = 0; r < 4; ++r) {
            int i = tid + r * 256, n = i >> 3, ch = i & 7;
            asm volatile("cp.async.cg.shared.global [%0], [%1], 16;"
                :: "r"(dst + n * 144 + ch * 16), "l"(src + (size_t)n * KTOT + ch * 8));
        }
        asm volatile("cp.async.commit_group;" ::: "memory");
    }

    float acc[2][8][4];
#pragma unroll
    for (int mf = 0; mf < 2; ++mf)
#pragma unroll
        for (int nf = 0; nf < 8; ++nf)
#pragma unroll
            for (int q = 0; q < 4; ++q) acc[mf][nf][q] = 0.0f;

    const uint32_t c0  = (uint32_t)((lane & 3) * 2);
    const uint32_t lmb = (uint32_t)((lane & 7) * 144 + (lane >> 3) * 16);
    const unsigned char* s_idx = smem + SM_IDX;
    const int rbase = ms * 32 + (lane >> 2);

    for (int s = 0; s < 32; ++s) {
        asm volatile("cp.async.wait_group 1;" ::: "memory");
        __syncthreads();
        uint32_t bufB = sb + SM_B + (s & 1) * BSTG;
#pragma unroll
        for (int cb = 0; cb < 4; ++cb) {
            int c = s * 4 + cb;
            const unsigned char* ip = s_idx + (c << 7) + rbase;
            uint32_t i0 = ip[0], i1 = ip[8], i2 = ip[16], i3 = ip[24];
            uint32_t t0 = i0 ^ c0, t1 = i1 ^ c0, t2 = i2 ^ c0, t3 = i3 ^ c0;
            uint32_t a00 = oh(t0),     a01 = oh(t1);
            uint32_t a02 = oh(t0 ^ 8), a03 = oh(t1 ^ 8);
            uint32_t a10 = oh(t2),     a11 = oh(t3);
            uint32_t a12 = oh(t2 ^ 8), a13 = oh(t3 ^ 8);
            uint32_t kb = bufB + (uint32_t)(cb * 32) + (uint32_t)(ns * 64 * 144) + lmb;
#pragma unroll
            for (int nf = 0; nf < 8; ++nf) {
                uint32_t b0, b1;
                asm volatile("ldmatrix.sync.aligned.m8n8.x2.shared.b16 {%0,%1}, [%2];"
                             : "=r"(b0), "=r"(b1) : "r"(kb + (uint32_t)(nf * 8 * 144)));
                MMA(acc[0][nf], a00, a01, a02, a03, b0, b1);
                MMA(acc[1][nf], a10, a11, a12, a13, b0, b1);
            }
        }
        __syncthreads();
        if (s + 2 < 32) {
            uint32_t dst = sb + SM_B + (s & 1) * BSTG;
            const __half* src = gB + (s + 2) * 64;
#pragma unroll
            for (int r = 0; r < 4; ++r) {
                int i = tid + r * 256, n = i >> 3, ch = i & 7;
                asm volatile("cp.async.cg.shared.global [%0], [%1], 16;"
                    :: "r"(dst + n * 144 + ch * 16), "l"(src + (size_t)n * KTOT + ch * 8));
            }
        }
        asm volatile("cp.async.commit_group;" ::: "memory");
    }

    const float* sbias = (const float*)(smem + SM_BIAS);
#pragma unroll
    for (int mf = 0; mf < 2; ++mf) {
        int row = m0 + ms * 32 + mf * 16 + (lane >> 2);
#pragma unroll
        for (int nf = 0; nf < 8; ++nf) {
            int colL = ns * 64 + nf * 8 + (int)c0;
            float2 bv = *(const float2*)(sbias + colL);
            float2 v0 = make_float2(acc[mf][nf][0] + bv.x, acc[mf][nf][1] + bv.y);
            float2 v1 = make_float2(acc[mf][nf][2] + bv.x, acc[mf][nf][3] + bv.y);
            *(float2*)(out + (size_t)row * OUT_DIM + o0 + colL) = v0;
            *(float2*)(out + (size_t)(row + 8) * OUT_DIM + o0 + colL) = v1;
        }
    }
}

// ---------------------------------------------------------------------------
extern "C" void kernel_launch(void* const* d_in, const int* in_sizes, int n_in,
                              void* d_out, int out_size)
{
    const float* x     = (const float*)d_in[0];
    const float* wgt   = (const float*)d_in[1];
    const float* cents = (const float*)d_in[2];
    const float* bias  = (const float*)d_in[3];
    float*       out   = (float*)d_out;

    cudaFuncSetAttribute(onehot_sp_kernel,
                         cudaFuncAttributeMaxDynamicSharedMemorySize, SM_TOT);
    cudaFuncSetAttribute(onehot_dense_kernel,
                         cudaFuncAttributeMaxDynamicSharedMemorySize, SM_TOT);

    probe_sp_kernel<<<1, 32>>>();
    quant_idx_kernel<<<dim3(N_TOK / 32, 4), 256>>>(x, cents);
    build_B_kernel<<<dim3(C_BOOKS, OUT_DIM / 256), 256>>>(wgt, cents);
    onehot_sp_kernel<<<dim3(OUT_DIM / 128, N_TOK / 128), 256, SM_TOT>>>(bias, out);
    onehot_dense_kernel<<<dim3(OUT_DIM / 128, N_TOK / 128), 256, SM_TOT>>>(bias, out);
}

// round 10
// speedup vs baseline: 4.5498x; 4.5498x over previous
#include <cuda_runtime.h>
#include <cuda_fp16.h>
#include <cstdint>

// Problem constants
#define N_TOK   4096
#define C_BOOKS 128
#define K_CENT  16
#define V_LEN   16
#define IN_DIM  2048
#define OUT_DIM 4096
#define KTOT    2048                   // 128 books * 16 centroids (one-hot K)

// Scratch (allocation-free rule: device globals)
__device__ unsigned char g_idxT[(size_t)C_BOOKS * N_TOK];   // [c][token]
__device__ __half g_Bt[(size_t)OUT_DIM * KTOT];             // [o][k] k-contiguous, 16 MB

// ---------------------------------------------------------------------------
__device__ __forceinline__ uint32_t smem_u32(const void* p) {
    uint32_t a;
    asm("{ .reg .u64 t; cvta.to.shared.u64 t, %1; cvt.u32.u64 %0, t; }" : "=r"(a) : "l"(p));
    return a;
}
// one-hot half2: t==0 -> (1,0), t==1 -> (0,1), else (0,0)
__device__ __forceinline__ uint32_t oh(uint32_t t) {
    return t == 0u ? 0x3C00u : (t == 1u ? 0x3C000000u : 0u);
}

// ---------------------------------------------------------------------------
// Fused prologue: blocks [0, 512) compute nearest-centroid indices (Chebyshev,
// exact vs reference argmin); blocks [512, 2560) build the fp16 LUT matrix
// g_Bt[o][c*16+k] = fp16( sum_v cents[c,k,v] * W[c*16+v, o] ).
// Independent outputs -> heterogeneous grid fills quant's idle issue slots.
// ---------------------------------------------------------------------------
__global__ void __launch_bounds__(256) prologue_kernel(
    const float* __restrict__ x, const float* __restrict__ wgt,
    const float* __restrict__ cents)
{
    __shared__ float sc[32 * 256];              // quant: 32 books; build: first 256 floats
    int tid = threadIdx.x;

    if (blockIdx.x < 512) {
        // ---- quant_idx part (identical math to the 26us R2 kernel) ----
        int blk  = blockIdx.x;
        int lane = tid & 31, w = tid >> 5;
        int token = (blk & 127) * 32 + lane;
        int cbase = (blk >> 7) * 32;

        for (int i = tid; i < 32 * 256; i += 256)
            sc[i] = cents[(size_t)cbase * 256 + i];
        __syncthreads();

        const float* xrow = x + (size_t)token * IN_DIM;
        for (int cl = w * 4; cl < w * 4 + 4; ++cl) {
            int c = cbase + cl;
            float xv[16];
            const float4* xp = (const float4*)(xrow + c * V_LEN);
#pragma unroll
            for (int q = 0; q < 4; ++q) {
                float4 t = xp[q];
                xv[q*4+0] = t.x; xv[q*4+1] = t.y; xv[q*4+2] = t.z; xv[q*4+3] = t.w;
            }
            const float4* cb = (const float4*)(sc + cl * 256);
            float best = 3.4028235e38f; int bi = 0;
#pragma unroll
            for (int k = 0; k < K_CENT; ++k) {
                float d = 0.0f;
#pragma unroll
                for (int q = 0; q < 4; ++q) {
                    float4 t = cb[k * 4 + q];
                    d = fmaxf(d, fabsf(xv[q*4+0] - t.x));
                    d = fmaxf(d, fabsf(xv[q*4+1] - t.y));
                    d = fmaxf(d, fabsf(xv[q*4+2] - t.z));
                    d = fmaxf(d, fabsf(xv[q*4+3] - t.w));
                }
                if (d < best) { best = d; bi = k; }   // strict < == first min (argmin)
            }
            g_idxT[(size_t)c * N_TOK + token] = (unsigned char)bi;
        }
    } else {
        // ---- build_B part (identical math to the prior build_B_kernel) ----
        int blk = blockIdx.x - 512;               // 0..2047
        int c   = blk & 127;                      // codebook
        int o   = (blk >> 7) * 256 + tid;         // output column
        sc[tid] = cents[(size_t)c * 256 + tid];
        __syncthreads();

        float acc[K_CENT];
#pragma unroll
        for (int k = 0; k < K_CENT; ++k) acc[k] = 0.0f;
#pragma unroll
        for (int v = 0; v < V_LEN; ++v) {
            float wv = wgt[(size_t)(c * V_LEN + v) * OUT_DIM + o];
#pragma unroll
            for (int k = 0; k < K_CENT; ++k)
                acc[k] = fmaf(sc[k * V_LEN + v], wv, acc[k]);
        }
        __half2 h[8];
#pragma unroll
        for (int j = 0; j < 8; ++j)
            h[j] = __floats2half2_rn(acc[2 * j], acc[2 * j + 1]);
        uint4* dst = (uint4*)(g_Bt + (size_t)o * KTOT + c * 16);
        dst[0] = *(uint4*)&h[0];
        dst[1] = *(uint4*)&h[4];
    }
}

// ---------------------------------------------------------------------------
// Dense one-hot GEMM via mma.sync m16n8k16 — verbatim R4 (best-known 188us).
// CTA 128 tok x 128 out, 256 thr (8 warps, warp tile 32x64), 2-stage cp.async.
// ---------------------------------------------------------------------------
#define SM_IDX  0                       // 128 books x 128 tokens = 16 KB
#define BSTG    (128 * 144)             // 18432 B per stage
#define SM_B    16384
#define SM_BIAS (SM_B + 2 * BSTG)       // 53248
#define SM_TOT  (SM_BIAS + 512)         // 53760

#define MMA(d, a0, a1, a2, a3, b0, b1) \
    asm volatile("mma.sync.aligned.m16n8k16.row.col.f32.f16.f16.f32 " \
        "{%0,%1,%2,%3}, {%4,%5,%6,%7}, {%8,%9}, {%0,%1,%2,%3};" \
        : "+f"((d)[0]), "+f"((d)[1]), "+f"((d)[2]), "+f"((d)[3]) \
        : "r"(a0), "r"(a1), "r"(a2), "r"(a3), "r"(b0), "r"(b1))

__global__ void __launch_bounds__(256, 1) onehot_hmma_kernel(
    const float* __restrict__ bias, float* __restrict__ out)
{
    extern __shared__ __align__(128) unsigned char smem[];
    const uint32_t sb = smem_u32(smem);
    const int tid = threadIdx.x, lane = tid & 31, w = tid >> 5;
    const int ms = w & 3, ns = w >> 2;          // 4 m-strips x 2 n-strips
    const int m0 = blockIdx.y * 128, o0 = blockIdx.x * 128;

    // Stage idx (128 books x 128 tokens) + bias
    {
        uint4* si = (uint4*)(smem + SM_IDX);
        for (int i = tid; i < 1024; i += 256)
            si[i] = *(const uint4*)(g_idxT + ((size_t)(i >> 3) << 12) + m0 + (i & 7) * 16);
        float* sbias = (float*)(smem + SM_BIAS);
        if (tid < 128) sbias[tid] = bias[o0 + tid];
    }

    const __half* gB = g_Bt + (size_t)o0 * KTOT;

    // Prologue: stages 0, 1
#pragma unroll
    for (int s = 0; s < 2; ++s) {
        uint32_t dst = sb + SM_B + s * BSTG;
        const __half* src = gB + s * 64;
#pragma unroll
        for (int r = 0; r < 4; ++r) {
            int i = tid + r * 256, n = i >> 3, ch = i & 7;
            asm volatile("cp.async.cg.shared.global [%0], [%1], 16;"
                :: "r"(dst + n * 144 + ch * 16), "l"(src + (size_t)n * KTOT + ch * 8));
        }
        asm volatile("cp.async.commit_group;" ::: "memory");
    }

    float acc[2][8][4];
#pragma unroll
    for (int mf = 0; mf < 2; ++mf)
#pragma unroll
        for (int nf = 0; nf < 8; ++nf)
#pragma unroll
            for (int q = 0; q < 4; ++q) acc[mf][nf][q] = 0.0f;

    const uint32_t c0  = (uint32_t)((lane & 3) * 2);
    const uint32_t lmb = (uint32_t)((lane & 7) * 144 + (lane >> 3) * 16);
    const unsigned char* s_idx = smem + SM_IDX;
    const int rbase = ms * 32 + (lane >> 2);

    for (int s = 0; s < 32; ++s) {
        asm volatile("cp.async.wait_group 1;" ::: "memory");
        __syncthreads();
        uint32_t bufB = sb + SM_B + (s & 1) * BSTG;
#pragma unroll
        for (int cb = 0; cb < 4; ++cb) {
            int c = s * 4 + cb;
            const unsigned char* ip = s_idx + (c << 7) + rbase;
            uint32_t i0 = ip[0], i1 = ip[8], i2 = ip[16], i3 = ip[24];
            uint32_t t0 = i0 ^ c0, t1 = i1 ^ c0, t2 = i2 ^ c0, t3 = i3 ^ c0;
            uint32_t a00 = oh(t0),     a01 = oh(t1);
            uint32_t a02 = oh(t0 ^ 8), a03 = oh(t1 ^ 8);
            uint32_t a10 = oh(t2),     a11 = oh(t3);
            uint32_t a12 = oh(t2 ^ 8), a13 = oh(t3 ^ 8);
            uint32_t kb = bufB + (uint32_t)(cb * 32) + (uint32_t)(ns * 64 * 144) + lmb;
#pragma unroll
            for (int nf = 0; nf < 8; ++nf) {
                uint32_t b0, b1;
                asm volatile("ldmatrix.sync.aligned.m8n8.x2.shared.b16 {%0,%1}, [%2];"
                             : "=r"(b0), "=r"(b1) : "r"(kb + (uint32_t)(nf * 8 * 144)));
                MMA(acc[0][nf], a00, a01, a02, a03, b0, b1);
                MMA(acc[1][nf], a10, a11, a12, a13, b0, b1);
            }
        }
        __syncthreads();
        if (s + 2 < 32) {
            uint32_t dst = sb + SM_B + (s & 1) * BSTG;
            const __half* src = gB + (s + 2) * 64;
#pragma unroll
            for (int r = 0; r < 4; ++r) {
                int i = tid + r * 256, n = i >> 3, ch = i & 7;
                asm volatile("cp.async.cg.shared.global [%0], [%1], 16;"
                    :: "r"(dst + n * 144 + ch * 16), "l"(src + (size_t)n * KTOT + ch * 8));
            }
        }
        asm volatile("cp.async.commit_group;" ::: "memory");
    }

    // Epilogue: add bias, store
    const float* sbias = (const float*)(smem + SM_BIAS);
#pragma unroll
    for (int mf = 0; mf < 2; ++mf) {
        int row = m0 + ms * 32 + mf * 16 + (lane >> 2);
#pragma unroll
        for (int nf = 0; nf < 8; ++nf) {
            int colL = ns * 64 + nf * 8 + (int)c0;
            float2 bv = *(const float2*)(sbias + colL);
            float2 v0 = make_float2(acc[mf][nf][0] + bv.x, acc[mf][nf][1] + bv.y);
            float2 v1 = make_float2(acc[mf][nf][2] + bv.x, acc[mf][nf][3] + bv.y);
            *(float2*)(out + (size_t)row * OUT_DIM + o0 + colL) = v0;
            *(float2*)(out + (size_t)(row + 8) * OUT_DIM + o0 + colL) = v1;
        }
    }
}

// ---------------------------------------------------------------------------
extern "C" void kernel_launch(void* const* d_in, const int* in_sizes, int n_in,
                              void* d_out, int out_size)
{
    const float* x     = (const float*)d_in[0];
    const float* wgt   = (const float*)d_in[1];
    const float* cents = (const float*)d_in[2];
    const float* bias  = (const float*)d_in[3];
    float*       out   = (float*)d_out;

    cudaFuncSetAttribute(onehot_hmma_kernel,
                         cudaFuncAttributeMaxDynamicSharedMemorySize, SM_TOT);

    prologue_kernel<<<2560, 256>>>(x, wgt, cents);
    onehot_hmma_kernel<<<dim3(OUT_DIM / 128, N_TOK / 128), 256, SM_TOT>>>(bias, out);
}